// round 8
// baseline (speedup 1.0000x reference)
#include <cuda_runtime.h>

#define NB 128
#define THREADS 1024
#define NITER 60
#define TS_R 129        // rowtab stride (129 % 32 == 1)
#define TS_C 131        // coltab stride (131 % 32 == 3), swizzled indices reach 130

typedef unsigned long long ull;

__device__ __forceinline__ ull pk2(float lo, float hi) {
    ull r; asm("mov.b64 %0, {%1, %2};" : "=l"(r) : "f"(lo), "f"(hi)); return r;
}
__device__ __forceinline__ void upk2(ull v, float& lo, float& hi) {
    asm("mov.b64 {%0, %1}, %2;" : "=f"(lo), "=f"(hi) : "l"(v));
}
__device__ __forceinline__ ull padd2(ull a, ull b) {
    ull r; asm("add.rn.f32x2 %0, %1, %2;" : "=l"(r) : "l"(a), "l"(b)); return r;
}
__device__ __forceinline__ ull psub2(ull a, ull b) {
    ull r; asm("sub.rn.f32x2 %0, %1, %2;" : "=l"(r) : "l"(a), "l"(b)); return r;
}

__global__ void __launch_bounds__(THREADS, 1)
gfusedmax_kernel(const float* __restrict__ x,
                 const float* __restrict__ A,
                 float* __restrict__ out)
{
    const int b     = blockIdx.x;
    const int tid   = threadIdx.x;
    const int lane  = tid & 31;
    const int warp  = tid >> 5;
    const int rbase = warp * 4;            // warp w owns rows 4w..4w+3; lane L owns cols 4L..4L+3

    __shared__ float rowtab[32 * TS_R];            // [contrib lane][row j]
    __shared__ float coltab[32 * TS_C];            // [contrib warp][swz(col j)]
    __shared__ __align__(16) float sy_row[NB];     // step * y
    __shared__ float ys_s[NB];
    __shared__ float sorted_s[NB];
    __shared__ float csum[2][NB];
    __shared__ int   rankp[8][NB];
    __shared__ float wsum[4], wcnt[4];

    const float step = 1.0f / 256.0f;

    // ---- clip bounds: lane L owns cols 4L..4L+3 (float4 loads, coalesced) ----
    float4 wv[4];
    ull z2[4][2];
    const float* Ab = A + (size_t)b * NB * NB;
    #pragma unroll
    for (int r = 0; r < 4; ++r) {
        wv[r] = *reinterpret_cast<const float4*>(&Ab[(size_t)(rbase + r) * NB + 4 * lane]);
        z2[r][0] = 0ULL;
        z2[r][1] = 0ULL;
    }

    // ---- phase-B identity: 256 threads, 2 per output j ----
    const int j  = tid >> 1;                       // valid for tid < 256
    const int h  = tid & 1;                        // contributor half (16 each)
    const int sj = (j & 127) + ((j & 127) >> 5);   // swizzled column index
    float xr = 0.0f;
    const float* rrd = &rowtab[(16 * h) * TS_R + (j & 127)];
    const float* crd = &coltab[(16 * h) * TS_C + sj];
    if (tid < 256) {
        xr = x[(size_t)b * NB + j];
        if (h == 0) sy_row[j] = step * xr;
    }

    // phase-A store addresses (precomputed)
    float* rw = &rowtab[lane * TS_R + 4 * warp];                 // rowtab[lane][4w + r]
    float* cw = &coltab[warp * TS_C + 4 * lane + (lane >> 3)];   // coltab[warp][swz(4L + c)]

    __syncthreads();

    // ---- 60 projected-gradient iterations ----
    #pragma unroll 1
    for (int it = 0; it < NITER; ++it) {
        // ===== phase A: z update + per-(lane,warp) partials =====
        float4 sc4 = *reinterpret_cast<const float4*>(&sy_row[4 * lane]);  // LDS.128 c-free
        float4 s4  = *reinterpret_cast<const float4*>(&sy_row[rbase]);     // broadcast
        ull c2_0 = pk2(sc4.x, sc4.y);
        ull c2_1 = pk2(sc4.z, sc4.w);
        const float syr[4] = {s4.x, s4.y, s4.z, s4.w};

        ull ca0, ca1;

        #pragma unroll
        for (int r = 0; r < 4; ++r) {
            ull s2 = pk2(syr[r], syr[r]);
            // cols (4L, 4L+1)
            ull v0 = padd2(z2[r][0], psub2(s2, c2_0));
            float ax, ay; upk2(v0, ax, ay);
            ax = fminf(fmaxf(ax, -wv[r].x), wv[r].x);
            ay = fminf(fmaxf(ay, -wv[r].y), wv[r].y);
            ull zz0 = pk2(ax, ay);
            z2[r][0] = zz0;
            // cols (4L+2, 4L+3)
            ull v1 = padd2(z2[r][1], psub2(s2, c2_1));
            float bx, by; upk2(v1, bx, by);
            bx = fminf(fmaxf(bx, -wv[r].z), wv[r].z);
            by = fminf(fmaxf(by, -wv[r].w), wv[r].w);
            ull zz1 = pk2(bx, by);
            z2[r][1] = zz1;
            // col accumulators (no add-to-zero)
            if (r == 0) { ca0 = zz0; ca1 = zz1; }
            else        { ca0 = padd2(ca0, zz0); ca1 = padd2(ca1, zz1); }
            // row partial: horizontal sum of this lane's 4 cols in row rbase+r
            ull rs2 = padd2(zz0, zz1);
            float rl, rh; upk2(rs2, rl, rh);
            rw[r] = rl + rh;                      // STS spread across the loop
        }

        // col partials: bank = 3w + 4L + c + (L>>3) -> conflict-free scalar stores
        {
            float c0v, c1v, c2v, c3v;
            upk2(ca0, c0v, c1v);
            upk2(ca1, c2v, c3v);
            cw[0] = c0v; cw[1] = c1v; cw[2] = c2v; cw[3] = c3v;
        }
        __syncthreads();

        // ===== phase B: 256 threads, 2 per j, 16 contribs each, ONE shuffle =====
        if (tid < 256) {
            float rs, cs;
            {
                float t0 = rrd[0*TS_R] + rrd[1*TS_R], t1 = rrd[2*TS_R]  + rrd[3*TS_R];
                float t2 = rrd[4*TS_R] + rrd[5*TS_R], t3 = rrd[6*TS_R]  + rrd[7*TS_R];
                float t4 = rrd[8*TS_R] + rrd[9*TS_R], t5 = rrd[10*TS_R] + rrd[11*TS_R];
                float t6 = rrd[12*TS_R]+ rrd[13*TS_R],t7 = rrd[14*TS_R] + rrd[15*TS_R];
                rs = ((t0+t1)+(t2+t3)) + ((t4+t5)+(t6+t7));
            }
            {
                float t0 = crd[0*TS_C] + crd[1*TS_C], t1 = crd[2*TS_C]  + crd[3*TS_C];
                float t2 = crd[4*TS_C] + crd[5*TS_C], t3 = crd[6*TS_C]  + crd[7*TS_C];
                float t4 = crd[8*TS_C] + crd[9*TS_C], t5 = crd[10*TS_C] + crd[11*TS_C];
                float t6 = crd[12*TS_C]+ crd[13*TS_C],t7 = crd[14*TS_C] + crd[15*TS_C];
                cs = ((t0+t1)+(t2+t3)) + ((t4+t5)+(t6+t7));
            }
            float d = cs - rs;
            d += __shfl_xor_sync(0xffffffffu, d, 1);   // combine the two halves
            if (h == 0) sy_row[j] = step * (xr + d);   // y = x - rowsum + colsum
        }
        __syncthreads();
    }

    // ---- final y (exact: /256 then *256 is exponent-only) ----
    float yv = 0.0f;
    if (tid < NB) {
        yv = sy_row[tid] * 256.0f;
        ys_s[tid] = yv;
    }
    __syncthreads();

    // ---- sparsemax: parallel rank sort (branch-free, deterministic) ----
    {
        int i = tid & 127;
        int gg = tid >> 7;                // 8 groups of 16 comparisons
        float vi = ys_s[i];
        int rp = 0;
        #pragma unroll
        for (int jj = 0; jj < 16; ++jj) {
            int jc = gg * 16 + jj;
            float uj = ys_s[jc];
            rp += (uj > vi) || (uj == vi && jc < i);
        }
        rankp[gg][i] = rp;
    }
    __syncthreads();
    if (tid < NB) {
        int rank = ((rankp[0][tid] + rankp[1][tid]) + (rankp[2][tid] + rankp[3][tid]))
                 + ((rankp[4][tid] + rankp[5][tid]) + (rankp[6][tid] + rankp[7][tid]));
        sorted_s[rank] = yv;              // descending
    }
    __syncthreads();

    // inclusive scan (Hillis-Steele, ping-pong)
    if (tid < NB) csum[0][tid] = sorted_s[tid];
    __syncthreads();
    int src = 0;
    for (int off = 1; off < NB; off <<= 1) {
        if (tid < NB) {
            float vv = csum[src][tid];
            if (tid >= off) vv += csum[src][tid - off];
            csum[1 - src][tid] = vv;
        }
        __syncthreads();
        src = 1 - src;
    }

    // mask + deterministic (sum, count) reduction (no f32 REDUX on sm_103a)
    if (tid < NB) {
        float s  = sorted_s[tid];
        float cu = csum[src][tid];
        float k  = (float)(tid + 1);
        bool  m  = (1.0f + k * s > cu);
        float sv = m ? s : 0.0f;
        float sc = m ? 1.0f : 0.0f;
        #pragma unroll
        for (int sft = 16; sft > 0; sft >>= 1) {
            sv += __shfl_xor_sync(0xffffffffu, sv, sft);
            sc += __shfl_xor_sync(0xffffffffu, sc, sft);
        }
        if (lane == 0) { wsum[warp] = sv; wcnt[warp] = sc; }
    }
    __syncthreads();

    if (tid < NB) {
        float ssum = ((wsum[0] + wsum[1]) + (wsum[2] + wsum[3]));
        float scnt = ((wcnt[0] + wcnt[1]) + (wcnt[2] + wcnt[3]));
        float tau  = (ssum - 1.0f) / scnt;
        out[(size_t)b * NB + tid] = fmaxf(yv - tau, 0.0f);
    }
}

extern "C" void kernel_launch(void* const* d_in, const int* in_sizes, int n_in,
                              void* d_out, int out_size)
{
    const float* x = (const float*)d_in[0];   // [B, 128]
    const float* A = (const float*)d_in[1];   // [B, 128, 128]
    float* out = (float*)d_out;               // [B, 128] float32

    int B = in_sizes[0] / NB;                 // 4096
    gfusedmax_kernel<<<B, THREADS>>>(x, A, out);
}

// round 9
// speedup vs baseline: 1.0019x; 1.0019x over previous
#include <cuda_runtime.h>

#define NB 128
#define THREADS 1024
#define NITER 60
#define TS_R 36         // rowtab2 stride: [row j][contrib], 36%32==4; float4-aligned reads
#define TS_C 131        // coltab stride (131 % 32 == 3), swizzled indices reach 130

typedef unsigned long long ull;

__device__ __forceinline__ ull pk2(float lo, float hi) {
    ull r; asm("mov.b64 %0, {%1, %2};" : "=l"(r) : "f"(lo), "f"(hi)); return r;
}
__device__ __forceinline__ void upk2(ull v, float& lo, float& hi) {
    asm("mov.b64 {%0, %1}, %2;" : "=f"(lo), "=f"(hi) : "l"(v));
}
__device__ __forceinline__ ull padd2(ull a, ull b) {
    ull r; asm("add.rn.f32x2 %0, %1, %2;" : "=l"(r) : "l"(a), "l"(b)); return r;
}
__device__ __forceinline__ ull psub2(ull a, ull b) {
    ull r; asm("sub.rn.f32x2 %0, %1, %2;" : "=l"(r) : "l"(a), "l"(b)); return r;
}

__global__ void __launch_bounds__(THREADS, 1)
gfusedmax_kernel(const float* __restrict__ x,
                 const float* __restrict__ A,
                 float* __restrict__ out)
{
    const int b     = blockIdx.x;
    const int tid   = threadIdx.x;
    const int lane  = tid & 31;
    const int warp  = tid >> 5;
    const int rbase = warp * 4;            // warp w owns rows 4w..4w+3; lane L owns cols 4L..4L+3

    __shared__ __align__(16) float rowtab2[NB * TS_R];   // [row j][contrib lane]  (18 KB)
    __shared__ float coltab[32 * TS_C];                  // [contrib warp][swz(col j)]
    __shared__ __align__(16) float sy_row[NB];           // step * y
    __shared__ float ys_s[NB];
    __shared__ float sorted_s[NB];
    __shared__ float csum[2][NB];
    __shared__ int   rankp[8][NB];
    __shared__ float wsum[4], wcnt[4];

    const float step = 1.0f / 256.0f;

    // ---- clip bounds: lane L owns cols 4L..4L+3 (float4 loads, coalesced) ----
    float4 wv[4];
    ull z2[4][2];
    const float* Ab = A + (size_t)b * NB * NB;
    #pragma unroll
    for (int r = 0; r < 4; ++r) {
        wv[r] = *reinterpret_cast<const float4*>(&Ab[(size_t)(rbase + r) * NB + 4 * lane]);
        z2[r][0] = 0ULL;
        z2[r][1] = 0ULL;
    }

    // ---- phase-B identity: j = tid>>3 (target index), g = tid&7 (contributor group) ----
    const int j  = tid >> 3;
    const int g  = tid & 7;
    const int sj = j + (j >> 5);                   // swizzled column index (max 130)
    const float xq = x[(size_t)b * NB + j];        // 8-lane broadcast load, coalesced

    // phase-A store bases
    float* rw = &rowtab2[(4 * warp) * TS_R + lane];              // rowtab2[4w + r][lane]
    float* cw = &coltab[warp * TS_C + 4 * lane + (lane >> 3)];   // coltab[warp][swz(4L + c)]
    // phase-B load bases
    const float4* rrd4 = reinterpret_cast<const float4*>(&rowtab2[j * TS_R + 4 * g]);
    const float*  crd  = &coltab[(4 * g) * TS_C + sj];

    if (g == 0) sy_row[j] = step * xq;
    __syncthreads();

    // ---- 60 projected-gradient iterations ----
    #pragma unroll 1
    for (int it = 0; it < NITER; ++it) {
        // ===== phase A: z update + per-(lane,warp) partials =====
        float4 sc4 = *reinterpret_cast<const float4*>(&sy_row[4 * lane]);  // LDS.128 c-free
        float4 s4  = *reinterpret_cast<const float4*>(&sy_row[rbase]);     // broadcast
        ull c2_0 = pk2(sc4.x, sc4.y);
        ull c2_1 = pk2(sc4.z, sc4.w);
        const float syr[4] = {s4.x, s4.y, s4.z, s4.w};

        ull ca0, ca1;

        #pragma unroll
        for (int r = 0; r < 4; ++r) {
            ull s2 = pk2(syr[r], syr[r]);
            // cols (4L, 4L+1)
            ull v0 = padd2(z2[r][0], psub2(s2, c2_0));
            float ax, ay; upk2(v0, ax, ay);
            ax = fminf(fmaxf(ax, -wv[r].x), wv[r].x);
            ay = fminf(fmaxf(ay, -wv[r].y), wv[r].y);
            ull zz0 = pk2(ax, ay);
            z2[r][0] = zz0;
            // cols (4L+2, 4L+3)
            ull v1 = padd2(z2[r][1], psub2(s2, c2_1));
            float bx, by; upk2(v1, bx, by);
            bx = fminf(fmaxf(bx, -wv[r].z), wv[r].z);
            by = fminf(fmaxf(by, -wv[r].w), wv[r].w);
            ull zz1 = pk2(bx, by);
            z2[r][1] = zz1;
            // col accumulators (no add-to-zero)
            if (r == 0) { ca0 = zz0; ca1 = zz1; }
            else        { ca0 = padd2(ca0, zz0); ca1 = padd2(ca1, zz1); }
            // row partial for row 4w+r: bank = 16w + 4r + lane -> conflict-free
            ull rs2 = padd2(zz0, zz1);
            float rl, rh; upk2(rs2, rl, rh);
            rw[r * TS_R] = rl + rh;
        }

        // col partials: bank = 3w + 4L + c + (L>>3) -> conflict-free scalar stores
        {
            float c0v, c1v, c2v, c3v;
            upk2(ca0, c0v, c1v);
            upk2(ca1, c2v, c3v);
            cw[0] = c0v; cw[1] = c1v; cw[2] = c2v; cw[3] = c3v;
        }
        __syncthreads();

        // ===== phase B: 8 threads per j; rows via ONE LDS.128, cols via 4 scalar =====
        float4 rq = *rrd4;                                   // contribs 4g..4g+3
        float rs = (rq.x + rq.y) + (rq.z + rq.w);
        float c0 = crd[0 * TS_C], c1 = crd[1 * TS_C], c2 = crd[2 * TS_C], c3 = crd[3 * TS_C];
        float d = ((c0 + c1) + (c2 + c3)) - rs;
        d += __shfl_xor_sync(0xffffffffu, d, 1);
        d += __shfl_xor_sync(0xffffffffu, d, 2);
        d += __shfl_xor_sync(0xffffffffu, d, 4);
        if (g == 0) sy_row[j] = step * (xq + d);             // y = x - rowsum + colsum
        __syncthreads();
    }

    // ---- final y (exact: /256 then *256 is exponent-only) ----
    float yv = 0.0f;
    if (tid < NB) {
        yv = sy_row[tid] * 256.0f;
        ys_s[tid] = yv;
    }
    __syncthreads();

    // ---- sparsemax: parallel rank sort (branch-free, deterministic) ----
    {
        int i = tid & 127;
        int gg = tid >> 7;                // 8 groups of 16 comparisons
        float vi = ys_s[i];
        int rp = 0;
        #pragma unroll
        for (int jj = 0; jj < 16; ++jj) {
            int jc = gg * 16 + jj;
            float uj = ys_s[jc];
            rp += (uj > vi) || (uj == vi && jc < i);
        }
        rankp[gg][i] = rp;
    }
    __syncthreads();
    if (tid < NB) {
        int rank = ((rankp[0][tid] + rankp[1][tid]) + (rankp[2][tid] + rankp[3][tid]))
                 + ((rankp[4][tid] + rankp[5][tid]) + (rankp[6][tid] + rankp[7][tid]));
        sorted_s[rank] = yv;              // descending
    }
    __syncthreads();

    // inclusive scan (Hillis-Steele, ping-pong)
    if (tid < NB) csum[0][tid] = sorted_s[tid];
    __syncthreads();
    int src = 0;
    for (int off = 1; off < NB; off <<= 1) {
        if (tid < NB) {
            float vv = csum[src][tid];
            if (tid >= off) vv += csum[src][tid - off];
            csum[1 - src][tid] = vv;
        }
        __syncthreads();
        src = 1 - src;
    }

    // mask + deterministic (sum, count) reduction (no f32 REDUX on sm_103a)
    if (tid < NB) {
        float s  = sorted_s[tid];
        float cu = csum[src][tid];
        float k  = (float)(tid + 1);
        bool  m  = (1.0f + k * s > cu);
        float sv = m ? s : 0.0f;
        float sc = m ? 1.0f : 0.0f;
        #pragma unroll
        for (int sft = 16; sft > 0; sft >>= 1) {
            sv += __shfl_xor_sync(0xffffffffu, sv, sft);
            sc += __shfl_xor_sync(0xffffffffu, sc, sft);
        }
        if (lane == 0) { wsum[warp] = sv; wcnt[warp] = sc; }
    }
    __syncthreads();

    if (tid < NB) {
        float ssum = ((wsum[0] + wsum[1]) + (wsum[2] + wsum[3]));
        float scnt = ((wcnt[0] + wcnt[1]) + (wcnt[2] + wcnt[3]));
        float tau  = (ssum - 1.0f) / scnt;
        out[(size_t)b * NB + tid] = fmaxf(yv - tau, 0.0f);
    }
}

extern "C" void kernel_launch(void* const* d_in, const int* in_sizes, int n_in,
                              void* d_out, int out_size)
{
    const float* x = (const float*)d_in[0];   // [B, 128]
    const float* A = (const float*)d_in[1];   // [B, 128, 128]
    float* out = (float*)d_out;               // [B, 128] float32

    int B = in_sizes[0] / NB;                 // 4096
    gfusedmax_kernel<<<B, THREADS>>>(x, A, out);
}